// round 15
// baseline (speedup 1.0000x reference)
#include <cuda_runtime.h>
#include <cuda_fp16.h>
#include <math.h>
#include <stdint.h>

#define NN    30000
#define EE    480000
#define HIDN  256
#define NLAY  6

// ---------------- static device scratch ----------------
static __device__ __align__(128) __half g_hh[2][NN * HIDN];   // h split hi (fp16)
static __device__ __align__(128) __half g_hl[2][NN * HIDN];   // h split lo (fp16)
static __device__ __align__(128) __half g_xlh[NN * HIDN];     // xl (fp16, attention-only)
static __device__ __align__(128) __half g_xrh[NN * HIDN];     // xr (fp16, attention-only)
static __device__ __align__(128) float  g_t[NN * 128];
static __device__ __align__(128) __half g_WTh[(NLAY * 512 + 128) * 256];
static __device__ __align__(128) __half g_WTl[(NLAY * 512 + 128) * 256];
static __device__ __align__(128) float  g_B[NLAY * 10 * 256];
static __device__ __align__(128) float  g_c[NLAY * 256];
static __device__ __align__(128) float  g_A[NLAY * 10 * 256];
static __device__ __align__(128) float  g_d[NLAY * 256];
static __device__ int g_cnt[NN + 1];
static __device__ int g_start[NN + 1];
static __device__ int g_cursor[NN + 1];
static __device__ int g_eid[EE];
// dst-sorted edge data (built once)
static __device__ __align__(128) int     g_srcs[EE];
static __device__ __align__(128) __half2 g_eah[EE * 12];   // duplicated half2, padded to 48B/edge

// ---------------- helpers ----------------
__device__ __forceinline__ void split_f16(float x, __half& hi, __half& lo) {
    hi = __float2half_rn(x);
    lo = __float2half_rn(x - __half2float(hi));
}

__device__ __forceinline__ uint32_t smem_u32(const void* p) {
    uint32_t a;
    asm("{ .reg .u64 t; cvta.to.shared.u64 t, %1; cvt.u32.u64 %0, t; }" : "=r"(a) : "l"(p));
    return a;
}

__device__ __forceinline__ void cp16(uint32_t dst, const void* src, int bytes) {
    asm volatile("cp.async.cg.shared.global [%0], [%1], 16, %2;"
                 :: "r"(dst), "l"(src), "r"(bytes));
}
__device__ __forceinline__ void cp_commit() {
    asm volatile("cp.async.commit_group;" ::: "memory");
}

__device__ __forceinline__ void mma_f16(float* d, const uint32_t* a, const uint32_t* b) {
    asm volatile(
        "mma.sync.aligned.m16n8k16.row.col.f32.f16.f16.f32 "
        "{%0,%1,%2,%3}, {%4,%5,%6,%7}, {%8,%9}, {%0,%1,%2,%3};"
        : "+f"(d[0]), "+f"(d[1]), "+f"(d[2]), "+f"(d[3])
        : "r"(a[0]), "r"(a[1]), "r"(a[2]), "r"(a[3]), "r"(b[0]), "r"(b[1]));
}

__device__ __forceinline__ void ldsm_x4(uint32_t* r, uint32_t addr) {
    asm volatile("ldmatrix.sync.aligned.m8n8.x4.shared.b16 {%0,%1,%2,%3}, [%4];"
                 : "=r"(r[0]), "=r"(r[1]), "=r"(r[2]), "=r"(r[3]) : "r"(addr));
}
__device__ __forceinline__ void ldsm_x2(uint32_t* r, uint32_t addr) {
    asm volatile("ldmatrix.sync.aligned.m8n8.x2.shared.b16 {%0,%1}, [%2];"
                 : "=r"(r[0]), "=r"(r[1]) : "r"(addr));
}

// ---------------- CSR build ----------------
__global__ void zero_kernel() {
    int i = blockIdx.x * 256 + threadIdx.x;
    if (i <= NN) g_cnt[i] = 0;
}
__global__ void count_kernel(const int* __restrict__ dst) {
    int e = blockIdx.x * 256 + threadIdx.x;
    if (e < EE) atomicAdd(&g_cnt[dst[e]], 1);
}
__global__ void scan_kernel() {
    __shared__ int part[1024];
    const int T = 1024, ITEMS = (NN + T - 1) / T;
    int tid = threadIdx.x, base = tid * ITEMS, s = 0;
    for (int i = 0; i < ITEMS; ++i) { int idx = base + i; if (idx < NN) s += g_cnt[idx]; }
    part[tid] = s;
    __syncthreads();
    for (int off = 1; off < T; off <<= 1) {
        int v = 0;
        if (tid >= off) v = part[tid - off];
        __syncthreads();
        part[tid] += v;
        __syncthreads();
    }
    int run = (tid == 0) ? 0 : part[tid - 1];
    for (int i = 0; i < ITEMS; ++i) {
        int idx = base + i;
        if (idx < NN) { g_start[idx] = run; g_cursor[idx] = run; run += g_cnt[idx]; }
    }
    if (tid == T - 1) g_start[NN] = part[T - 1];
}
__global__ void fill_kernel(const int* __restrict__ dst) {
    int e = blockIdx.x * 256 + threadIdx.x;
    if (e < EE) { int pos = atomicAdd(&g_cursor[dst[e]], 1); g_eid[pos] = e; }
}
// deterministic order: sort each node's list in a local buffer
__global__ void sort_kernel() {
    int n = blockIdx.x * 128 + threadIdx.x;
    if (n >= NN) return;
    int s0 = g_start[n], s1 = g_start[n + 1];
    int d = s1 - s0;
    if (d <= 1) return;
    if (d <= 96) {
        int buf[96];
        for (int i = 0; i < d; ++i) buf[i] = g_eid[s0 + i];
        for (int i = 1; i < d; ++i) {
            int v = buf[i], j = i - 1;
            while (j >= 0 && buf[j] > v) { buf[j + 1] = buf[j]; --j; }
            buf[j + 1] = v;
        }
        for (int i = 0; i < d; ++i) g_eid[s0 + i] = buf[i];
    } else {
        for (int i = s0 + 1; i < s1; ++i) {
            int v = g_eid[i], j = i - 1;
            while (j >= s0 && g_eid[j] > v) { g_eid[j + 1] = g_eid[j]; --j; }
            g_eid[j + 1] = v;
        }
    }
}
// materialize dst-sorted edge arrays (once); ea pre-packed as duplicated half2
__global__ void gather_kernel(const int* __restrict__ src,
                              const float* __restrict__ eattr) {
    int p = blockIdx.x * 256 + threadIdx.x;
    if (p >= EE) return;
    int e = g_eid[p];
    g_srcs[p] = src[e];
    const float* s = eattr + (size_t)e * 10;
    __half2* d = g_eah + (size_t)p * 12;
    #pragma unroll
    for (int j = 0; j < 10; ++j) d[j] = __float2half2_rn(s[j]);
    d[10] = __floats2half2_rn(0.f, 0.f);
    d[11] = __floats2half2_rn(0.f, 0.f);
}

// ---------------- edge-matrix chain precompute ----------------
__global__ void chain_kernel(const float* __restrict__ eW, const float* __restrict__ eb,
                             const float* __restrict__ Weu, const float* __restrict__ beu) {
    __shared__ float Ash[10 * 256];
    __shared__ float dsh[256];
    int tid = threadIdx.x;
    for (int t = tid; t < 2560; t += 256) Ash[t] = eW[t];
    dsh[tid] = eb[tid];
    __syncthreads();
    for (int i = 0; i < NLAY; ++i) {
        for (int t = tid; t < 2560; t += 256) g_A[i * 2560 + t] = Ash[t];
        g_d[i * 256 + tid] = dsh[tid];
        __syncthreads();
        if (i == NLAY - 1) break;
        const float* Wp = Weu + (size_t)i * 65536;
        float accA[10];
        #pragma unroll
        for (int k = 0; k < 10; ++k) accA[k] = 0.f;
        float accd = 0.f;
        for (int c = 0; c < 256; ++c) {
            float w = Wp[c * 256 + tid];
            accd = fmaf(dsh[c], w, accd);
            #pragma unroll
            for (int k = 0; k < 10; ++k) accA[k] = fmaf(Ash[k * 256 + c], w, accA[k]);
        }
        accd += beu[i * 256 + tid];
        __syncthreads();
        #pragma unroll
        for (int k = 0; k < 10; ++k) Ash[k * 256 + tid] = accA[k];
        dsh[tid] = accd;
        __syncthreads();
    }
}
__global__ void bmat_kernel(const float* __restrict__ We) {
    __shared__ float Ash[10 * 256];
    __shared__ float dsh[256];
    int i = blockIdx.x, tid = threadIdx.x;
    for (int t = tid; t < 2560; t += 256) Ash[t] = g_A[i * 2560 + t];
    dsh[tid] = g_d[i * 256 + tid];
    __syncthreads();
    const float* Wp = We + (size_t)i * 65536;
    float accB[10];
    #pragma unroll
    for (int k = 0; k < 10; ++k) accB[k] = 0.f;
    float accc = 0.f;
    for (int c = 0; c < 256; ++c) {
        float w = Wp[c * 256 + tid];
        accc = fmaf(dsh[c], w, accc);
        #pragma unroll
        for (int k = 0; k < 10; ++k) accB[k] = fmaf(Ash[k * 256 + c], w, accB[k]);
    }
    #pragma unroll
    for (int k = 0; k < 10; ++k) g_B[i * 2560 + k * 256 + tid] = accB[k];
    g_c[i * 256 + tid] = accc;
}

// ---------------- weight transpose + fp16 split ----------------
__global__ void wprep_kernel(const float* __restrict__ Wl, const float* __restrict__ Wr,
                             const float* __restrict__ oW1) {
    int idx = blockIdx.x * 256 + threadIdx.x;
    const int LTOT = NLAY * 512 * 256;
    float v;
    if (idx < LTOT) {
        int l = idx >> 17;
        int rem = idx & 131071;
        int row = rem >> 8, k = rem & 255;
        v = (row < 256) ? Wl[(size_t)l * 65536 + k * 256 + row]
                        : Wr[(size_t)l * 65536 + k * 256 + (row - 256)];
    } else if (idx < LTOT + 128 * 256) {
        int rem = idx - LTOT;
        int row = rem >> 8, k = rem & 255;
        v = oW1[k * 128 + row];
    } else return;
    __half hi, lo;
    split_f16(v, hi, lo);
    g_WTh[idx] = hi; g_WTl[idx] = lo;
}

// ---------------- node encoder ----------------
__global__ void encoder_kernel(const float* __restrict__ x, const float* __restrict__ nW,
                               const float* __restrict__ nb) {
    int idx = blockIdx.x * 256 + threadIdx.x;
    int n = idx >> 8, c = idx & 255;
    if (n >= NN) return;
    float s = nb[c];
    #pragma unroll
    for (int k = 0; k < 13; ++k) s = fmaf(x[n * 13 + k], nW[k * 256 + c], s);
    __half hi, lo;
    split_f16(s, hi, lo);
    g_hh[0][idx] = hi; g_hl[0][idx] = lo;
}

// ---------------- FP16 mma.sync GEMM: BM=128, BN=64, 8 warps (4m x 2n) ----------------
#define SA 40
#define A_ARR_H 5120
#define B_ARR_H 2560
#define BUF_H (2 * A_ARR_H + 2 * B_ARR_H)
#define OFF_AL A_ARR_H
#define OFF_BH (2 * A_ARR_H)
#define OFF_BL (2 * A_ARR_H + B_ARR_H)
#define GSMEM_BYTES (2 * BUF_H * 2)

__global__ __launch_bounds__(256, 3)
void mma_gemm(int hsel, int wrow0, const float* __restrict__ bias0,
              const float* __restrict__ bias1, int outmode, float slope, int passes) {
    extern __shared__ __align__(16) __half sm[];
    const __half* __restrict__ Ah = g_hh[hsel];
    const __half* __restrict__ Al = g_hl[hsel];

    int tid = threadIdx.x;
    int wid = tid >> 5, lane = tid & 31;
    int warp_m = wid & 3, warp_n = wid >> 2;
    int m0 = blockIdx.x * 128;
    int colg = blockIdx.y * 64;
    int tig = lane & 3, grp = lane >> 2;
    const bool lo_on = (passes == 3);

    int arow = (lane & 7) + ((lane >> 3) & 1) * 8;
    int acol = (lane >> 4) * 8;
    int brow = lane & 7;
    int bcol = ((lane >> 3) & 1) * 8;

    float c[2][4][4];
    #pragma unroll
    for (int mi = 0; mi < 2; ++mi)
        #pragma unroll
        for (int ni = 0; ni < 4; ++ni)
            #pragma unroll
            for (int j = 0; j < 4; ++j) c[mi][ni][j] = 0.f;

    auto issue = [&](int kb, int buf) {
        int kt = kb * 32;
        __half* base = sm + buf * BUF_H;
        #pragma unroll
        for (int i = 0; i < 2; ++i) {
            int slot = tid + i * 256;
            int r = slot >> 2, ch = slot & 3;
            int gm = m0 + r;
            int bytes = 16;
            if (gm >= NN) { gm = NN - 1; bytes = 0; }
            cp16(smem_u32(base + r * SA + ch * 8),
                 Ah + (size_t)gm * 256 + kt + ch * 8, bytes);
            if (lo_on)
                cp16(smem_u32(base + OFF_AL + r * SA + ch * 8),
                     Al + (size_t)gm * 256 + kt + ch * 8, bytes);
        }
        {
            int r = tid >> 2, ch = tid & 3;
            int row = wrow0 + colg + r;
            cp16(smem_u32(base + OFF_BH + r * SA + ch * 8),
                 g_WTh + (size_t)row * 256 + kt + ch * 8, 16);
            if (lo_on)
                cp16(smem_u32(base + OFF_BL + r * SA + ch * 8),
                     g_WTl + (size_t)row * 256 + kt + ch * 8, 16);
        }
        cp_commit();
    };

    issue(0, 0);
    for (int kb = 0; kb < 8; ++kb) {
        if (kb < 7) {
            issue(kb + 1, (kb + 1) & 1);
            asm volatile("cp.async.wait_group 1;" ::: "memory");
        } else {
            asm volatile("cp.async.wait_group 0;" ::: "memory");
        }
        __syncthreads();

        uint32_t sAh = smem_u32(sm + (kb & 1) * BUF_H);
        uint32_t sAl = sAh + OFF_AL * 2;
        uint32_t sBh = sAh + OFF_BH * 2;
        uint32_t sBl = sAh + OFF_BL * 2;

        #pragma unroll
        for (int ks = 0; ks < 2; ++ks) {
            int k0 = ks * 16;
            uint32_t bh[4][2], bl[4][2];
            #pragma unroll
            for (int ni = 0; ni < 4; ++ni) {
                uint32_t boff = (uint32_t)((warp_n * 32 + ni * 8 + brow) * SA + k0 + bcol) * 2;
                ldsm_x2(bh[ni], sBh + boff);
                if (lo_on) ldsm_x2(bl[ni], sBl + boff);
            }
            #pragma unroll
            for (int mi = 0; mi < 2; ++mi) {
                uint32_t aoff = (uint32_t)((warp_m * 32 + mi * 16 + arow) * SA + k0 + acol) * 2;
                uint32_t ah[4], al[4];
                ldsm_x4(ah, sAh + aoff);
                if (lo_on) ldsm_x4(al, sAl + aoff);
                #pragma unroll
                for (int ni = 0; ni < 4; ++ni) {
                    mma_f16(c[mi][ni], ah, bh[ni]);
                    if (lo_on) {
                        mma_f16(c[mi][ni], ah, bl[ni]);
                        mma_f16(c[mi][ni], al, bh[ni]);
                    }
                }
            }
        }
        __syncthreads();
    }

    #pragma unroll
    for (int mi = 0; mi < 2; ++mi) {
        #pragma unroll
        for (int ni = 0; ni < 4; ++ni) {
            int gn = colg + warp_n * 32 + ni * 8 + tig * 2;
            int gm = m0 + warp_m * 32 + mi * 16 + grp;
            int gm2 = gm + 8;
            if (outmode) {
                float b0v = bias0[gn], b1v = bias0[gn + 1];
                if (gm < NN) {
                    float v0 = c[mi][ni][0] + b0v; v0 = v0 >= 0.f ? v0 : slope * v0;
                    float v1 = c[mi][ni][1] + b1v; v1 = v1 >= 0.f ? v1 : slope * v1;
                    *(float2*)(g_t + (size_t)gm * 128 + gn) = make_float2(v0, v1);
                }
                if (gm2 < NN) {
                    float v0 = c[mi][ni][2] + b0v; v0 = v0 >= 0.f ? v0 : slope * v0;
                    float v1 = c[mi][ni][3] + b1v; v1 = v1 >= 0.f ? v1 : slope * v1;
                    *(float2*)(g_t + (size_t)gm2 * 128 + gn) = make_float2(v0, v1);
                }
            } else {
                __half* outp; const float* bp; int cc;
                if (gn < 256) { outp = g_xlh; bp = bias0; cc = gn; }
                else          { outp = g_xrh; bp = bias1; cc = gn - 256; }
                float b0v = bp[cc], b1v = bp[cc + 1];
                if (gm < NN) {
                    __half2 hv = __floats2half2_rn(c[mi][ni][0] + b0v, c[mi][ni][1] + b1v);
                    *(__half2*)(outp + (size_t)gm * 256 + cc) = hv;
                }
                if (gm2 < NN) {
                    __half2 hv = __floats2half2_rn(c[mi][ni][2] + b0v, c[mi][ni][3] + b1v);
                    *(__half2*)(outp + (size_t)gm2 * 256 + cc) = hv;
                }
            }
        }
    }
}

// ---------------- fused attention v7: occupancy-first (6 CTAs/SM) ----------------
// one warp per node; 1-edge loop (small working set); xr folded into c constant.
__global__ __launch_bounds__(128, 6)
void attn_fused(int layer, int hin,
                const float* __restrict__ att, const float* __restrict__ conv_b,
                const float* __restrict__ bng, const float* __restrict__ bnb,
                const float* __restrict__ bnrm, const float* __restrict__ bnrv) {
    int tid = threadIdx.x;
    int warp = tid >> 5, lane = tid & 31;
    int n = blockIdx.x * 4 + warp;
    if (n >= NN) return;
    int hout = hin ^ 1;
    int c0 = lane * 8;

    const __half2 zero2 = __floats2half2_rn(0.f, 0.f);
    const __half2 fifth2 = __floats2half2_rn(0.2f, 0.2f);

    __half2 Brg2[10][4];
    #pragma unroll
    for (int k = 0; k < 10; ++k) {
        float4 b0 = *(const float4*)(g_B + layer * 2560 + k * 256 + c0);
        float4 b1 = *(const float4*)(g_B + layer * 2560 + k * 256 + c0 + 4);
        Brg2[k][0] = __floats2half2_rn(b0.x, b0.y);
        Brg2[k][1] = __floats2half2_rn(b0.z, b0.w);
        Brg2[k][2] = __floats2half2_rn(b1.x, b1.y);
        Brg2[k][3] = __floats2half2_rn(b1.z, b1.w);
    }
    __half2 attr2[4], crx2[4];
    {
        float4 a0 = *(const float4*)(att + layer * 256 + c0);
        float4 a1 = *(const float4*)(att + layer * 256 + c0 + 4);
        attr2[0] = __floats2half2_rn(a0.x, a0.y);
        attr2[1] = __floats2half2_rn(a0.z, a0.w);
        attr2[2] = __floats2half2_rn(a1.x, a1.y);
        attr2[3] = __floats2half2_rn(a1.z, a1.w);
        float4 d0 = *(const float4*)(g_c + layer * 256 + c0);
        float4 d1 = *(const float4*)(g_c + layer * 256 + c0 + 4);
        uint4 rv4 = *(const uint4*)(g_xrh + (size_t)n * 256 + c0);
        // crx = c + xr (both loop-invariant for this node)
        crx2[0] = __hadd2(__floats2half2_rn(d0.x, d0.y), *(__half2*)&rv4.x);
        crx2[1] = __hadd2(__floats2half2_rn(d0.z, d0.w), *(__half2*)&rv4.y);
        crx2[2] = __hadd2(__floats2half2_rn(d1.x, d1.y), *(__half2*)&rv4.z);
        crx2[3] = __hadd2(__floats2half2_rn(d1.z, d1.w), *(__half2*)&rv4.w);
    }

    float accv[8];
    #pragma unroll
    for (int j = 0; j < 8; ++j) accv[j] = 0.f;
    float den = 0.f;

    int s0 = g_start[n], s1 = g_start[n + 1];
    for (int p = s0; p < s1; ++p) {
        int sn = g_srcs[p];
        uint4 xv = *(const uint4*)(g_xlh + (size_t)sn * 256 + c0);
        __half2 xl2[4];
        xl2[0] = *(__half2*)&xv.x; xl2[1] = *(__half2*)&xv.y;
        xl2[2] = *(__half2*)&xv.z; xl2[3] = *(__half2*)&xv.w;

        const uint4* ea4 = (const uint4*)(g_eah + (size_t)p * 12);
        uint4 u0 = ea4[0], u1 = ea4[1], u2 = ea4[2];
        __half2 ea[10];
        ea[0] = *(__half2*)&u0.x; ea[1] = *(__half2*)&u0.y;
        ea[2] = *(__half2*)&u0.z; ea[3] = *(__half2*)&u0.w;
        ea[4] = *(__half2*)&u1.x; ea[5] = *(__half2*)&u1.y;
        ea[6] = *(__half2*)&u1.z; ea[7] = *(__half2*)&u1.w;
        ea[8] = *(__half2*)&u2.x; ea[9] = *(__half2*)&u2.y;

        __half2 m2[4] = {crx2[0], crx2[1], crx2[2], crx2[3]};
        #pragma unroll
        for (int k = 0; k < 10; ++k)
            #pragma unroll
            for (int j2 = 0; j2 < 4; ++j2)
                m2[j2] = __hfma2(ea[k], Brg2[k][j2], m2[j2]);

        __half2 s2 = zero2;
        #pragma unroll
        for (int j2 = 0; j2 < 4; ++j2) {
            __half2 v2 = __hadd2(m2[j2], xl2[j2]);
            __half2 lk = __hfma2(__hmin2(v2, zero2), fifth2, __hmax2(v2, zero2));
            s2 = __hfma2(lk, attr2[j2], s2);
        }
        float2 sf = __half22float2(s2);
        float s = sf.x + sf.y;
        s += __shfl_xor_sync(0xffffffffu, s, 1);
        s += __shfl_xor_sync(0xffffffffu, s, 2);
        float w = __expf(s);
        den += w;
        #pragma unroll
        for (int j2 = 0; j2 < 4; ++j2) {
            float2 xf = __half22float2(xl2[j2]);
            accv[2 * j2]     = fmaf(w, xf.x, accv[2 * j2]);
            accv[2 * j2 + 1] = fmaf(w, xf.y, accv[2 * j2 + 1]);
        }
    }

    float invden = 1.f / (den + 1e-16f);

    float4 cb0 = *(const float4*)(conv_b + layer * 256 + c0);
    float4 cb1 = *(const float4*)(conv_b + layer * 256 + c0 + 4);
    float4 g0  = *(const float4*)(bng + layer * 256 + c0);
    float4 g1  = *(const float4*)(bng + layer * 256 + c0 + 4);
    float4 bb0 = *(const float4*)(bnb + layer * 256 + c0);
    float4 bb1 = *(const float4*)(bnb + layer * 256 + c0 + 4);
    float4 rm0 = *(const float4*)(bnrm + layer * 256 + c0);
    float4 rm1 = *(const float4*)(bnrm + layer * 256 + c0 + 4);
    float4 rv0 = *(const float4*)(bnrv + layer * 256 + c0);
    float4 rv1 = *(const float4*)(bnrv + layer * 256 + c0 + 4);
    float cb[8] = {cb0.x, cb0.y, cb0.z, cb0.w, cb1.x, cb1.y, cb1.z, cb1.w};
    float gg[8] = {g0.x, g0.y, g0.z, g0.w, g1.x, g1.y, g1.z, g1.w};
    float bbv[8] = {bb0.x, bb0.y, bb0.z, bb0.w, bb1.x, bb1.y, bb1.z, bb1.w};
    float rm[8] = {rm0.x, rm0.y, rm0.z, rm0.w, rm1.x, rm1.y, rm1.z, rm1.w};
    float rv[8] = {rv0.x, rv0.y, rv0.z, rv0.w, rv1.x, rv1.y, rv1.z, rv1.w};

    size_t base = (size_t)n * 256 + c0;
    __half resh[8], resl[8];
    if (layer >= 1) {
        *(uint4*)resh = *(const uint4*)(&g_hh[hin][base]);
        *(uint4*)resl = *(const uint4*)(&g_hl[hin][base]);
    }
    __half oh[8], ol[8];
    #pragma unroll
    for (int j = 0; j < 8; ++j) {
        float sc = gg[j] * rsqrtf(rv[j] + 1e-5f);
        float sh = bbv[j] - rm[j] * sc;
        float v = accv[j] * invden + cb[j];
        v = v * sc + sh;
        v = v >= 0.f ? v : 0.01f * v;
        if (layer >= 1) v += __half2float(resh[j]) + __half2float(resl[j]);
        split_f16(v, oh[j], ol[j]);
    }
    *(uint4*)(&g_hh[hout][base]) = *(const uint4*)oh;
    *(uint4*)(&g_hl[hout][base]) = *(const uint4*)ol;
}

// ---------------- head: out = t @ W2 + b2 ----------------
__global__ void head2_kernel(const float* __restrict__ W2, const float* __restrict__ b2,
                             float* __restrict__ out) {
    __shared__ float w[128];
    int tid = threadIdx.x;
    if (tid < 128) w[tid] = W2[tid];
    __syncthreads();
    int n = blockIdx.x * 256 + tid;
    if (n >= NN) return;
    float s = b2[0];
    const float* tp = g_t + (size_t)n * 128;
    #pragma unroll
    for (int j = 0; j < 128; ++j) s = fmaf(tp[j], w[j], s);
    out[n] = s;
}

// ---------------- launch ----------------
extern "C" void kernel_launch(void* const* d_in, const int* in_sizes, int n_in,
                              void* d_out, int out_size) {
    const float* x      = (const float*)d_in[0];
    const int*   ei     = (const int*)d_in[1];
    const float* eattr  = (const float*)d_in[2];
    const float* nW     = (const float*)d_in[3];
    const float* nb     = (const float*)d_in[4];
    const float* eW     = (const float*)d_in[5];
    const float* eb     = (const float*)d_in[6];
    const float* Wl     = (const float*)d_in[7];
    const float* bl     = (const float*)d_in[8];
    const float* Wr     = (const float*)d_in[9];
    const float* br     = (const float*)d_in[10];
    const float* We     = (const float*)d_in[11];
    const float* att    = (const float*)d_in[12];
    const float* conv_b = (const float*)d_in[13];
    const float* Weu    = (const float*)d_in[14];
    const float* beu    = (const float*)d_in[15];
    const float* bng    = (const float*)d_in[16];
    const float* bnb    = (const float*)d_in[17];
    const float* bnrm   = (const float*)d_in[18];
    const float* bnrv   = (const float*)d_in[19];
    const float* oW1    = (const float*)d_in[20];
    const float* ob1    = (const float*)d_in[21];
    const float* oW2    = (const float*)d_in[22];
    const float* ob2    = (const float*)d_in[23];

    const int* srcp = ei;
    const int* dstp = ei + EE;

    static int attr_set = 0;
    if (!attr_set) {
        cudaFuncSetAttribute(mma_gemm, cudaFuncAttributeMaxDynamicSharedMemorySize,
                             GSMEM_BYTES);
        attr_set = 1;
    }

    const int MT = (NN + 127) / 128;   // 235
    dim3 gemm_grid(MT, 8);
    dim3 head_grid(MT, 2);

    // --- mma_gemm L0 in the ncu capture slot (4th launch) ---
    wprep_kernel<<<3200, 256>>>(Wl, Wr, oW1);                     // 1
    encoder_kernel<<<NN, 256>>>(x, nW, nb);                       // 2
    zero_kernel<<<(NN + 256) / 256, 256>>>();                     // 3
    mma_gemm<<<gemm_grid, 256, GSMEM_BYTES>>>(0, 0, bl, br, 0, 1.0f, 1);  // 4 <- profiled

    // CSR build (deterministic) + sorted edge arrays
    count_kernel<<<(EE + 255) / 256, 256>>>(dstp);
    scan_kernel<<<1, 1024>>>();
    fill_kernel<<<(EE + 255) / 256, 256>>>(dstp);
    sort_kernel<<<(NN + 127) / 128, 128>>>();
    gather_kernel<<<(EE + 255) / 256, 256>>>(srcp, eattr);

    // edge matrix chain
    chain_kernel<<<1, 256>>>(eW, eb, Weu, beu);
    bmat_kernel<<<NLAY, 256>>>(We);

    int cur = 0;
    // layer 0 attention (GEMM L0 already issued above)
    attn_fused<<<(NN + 3) / 4, 128>>>(0, cur, att, conv_b, bng, bnb, bnrm, bnrv);
    cur ^= 1;
    for (int i = 1; i < NLAY; ++i) {
        mma_gemm<<<gemm_grid, 256, GSMEM_BYTES>>>(cur, i * 512, bl + i * 256, br + i * 256,
                                                  /*outmode=*/0, /*slope=*/1.0f, /*passes=*/1);
        attn_fused<<<(NN + 3) / 4, 128>>>(i, cur, att, conv_b, bng, bnb, bnrm, bnrv);
        cur ^= 1;
    }

    // output head (fp32-grade 3-pass)
    mma_gemm<<<head_grid, 256, GSMEM_BYTES>>>(cur, NLAY * 512, ob1, (const float*)0,
                                              /*outmode=*/1, /*slope=*/0.01f, /*passes=*/3);
    head2_kernel<<<(NN + 255) / 256, 256>>>(oW2, ob2, (float*)d_out);
}

// round 16
// speedup vs baseline: 1.1448x; 1.1448x over previous
#include <cuda_runtime.h>
#include <cuda_fp16.h>
#include <math.h>
#include <stdint.h>

#define NN    30000
#define EE    480000
#define HIDN  256
#define NLAY  6

// ---------------- static device scratch ----------------
static __device__ __align__(128) __half g_hh[2][NN * HIDN];   // h split hi (fp16)
static __device__ __align__(128) __half g_hl[2][NN * HIDN];   // h split lo (fp16)
static __device__ __align__(128) __half g_xlh[NN * HIDN];     // xl (fp16, attention-only)
static __device__ __align__(128) __half g_xrh[NN * HIDN];     // xr (fp16, attention-only)
static __device__ __align__(128) float  g_t[NN * 128];
static __device__ __align__(128) __half g_WTh[(NLAY * 512 + 128) * 256];
static __device__ __align__(128) __half g_WTl[(NLAY * 512 + 128) * 256];
static __device__ __align__(128) float  g_B[NLAY * 10 * 256];
static __device__ __align__(128) float  g_c[NLAY * 256];
static __device__ __align__(128) float  g_A[NLAY * 10 * 256];
static __device__ __align__(128) float  g_d[NLAY * 256];
static __device__ int g_cnt[NN + 1];
static __device__ int g_start[NN + 1];
static __device__ int g_cursor[NN + 1];
static __device__ int g_eid[EE];
// dst-sorted edge data (built once)
static __device__ __align__(128) int     g_srcs[EE];
static __device__ __align__(128) __half2 g_eah[EE * 12];   // duplicated half2, padded to 48B/edge

// ---------------- helpers ----------------
__device__ __forceinline__ void split_f16(float x, __half& hi, __half& lo) {
    hi = __float2half_rn(x);
    lo = __float2half_rn(x - __half2float(hi));
}

__device__ __forceinline__ uint32_t smem_u32(const void* p) {
    uint32_t a;
    asm("{ .reg .u64 t; cvta.to.shared.u64 t, %1; cvt.u32.u64 %0, t; }" : "=r"(a) : "l"(p));
    return a;
}

__device__ __forceinline__ void cp16(uint32_t dst, const void* src, int bytes) {
    asm volatile("cp.async.cg.shared.global [%0], [%1], 16, %2;"
                 :: "r"(dst), "l"(src), "r"(bytes));
}
__device__ __forceinline__ void cp_commit() {
    asm volatile("cp.async.commit_group;" ::: "memory");
}

__device__ __forceinline__ void mma_f16(float* d, const uint32_t* a, const uint32_t* b) {
    asm volatile(
        "mma.sync.aligned.m16n8k16.row.col.f32.f16.f16.f32 "
        "{%0,%1,%2,%3}, {%4,%5,%6,%7}, {%8,%9}, {%0,%1,%2,%3};"
        : "+f"(d[0]), "+f"(d[1]), "+f"(d[2]), "+f"(d[3])
        : "r"(a[0]), "r"(a[1]), "r"(a[2]), "r"(a[3]), "r"(b[0]), "r"(b[1]));
}

__device__ __forceinline__ void ldsm_x4(uint32_t* r, uint32_t addr) {
    asm volatile("ldmatrix.sync.aligned.m8n8.x4.shared.b16 {%0,%1,%2,%3}, [%4];"
                 : "=r"(r[0]), "=r"(r[1]), "=r"(r[2]), "=r"(r[3]) : "r"(addr));
}
__device__ __forceinline__ void ldsm_x2(uint32_t* r, uint32_t addr) {
    asm volatile("ldmatrix.sync.aligned.m8n8.x2.shared.b16 {%0,%1}, [%2];"
                 : "=r"(r[0]), "=r"(r[1]) : "r"(addr));
}

// ---------------- CSR build ----------------
__global__ void zero_kernel() {
    int i = blockIdx.x * 256 + threadIdx.x;
    if (i <= NN) g_cnt[i] = 0;
}
__global__ void count_kernel(const int* __restrict__ dst) {
    int e = blockIdx.x * 256 + threadIdx.x;
    if (e < EE) atomicAdd(&g_cnt[dst[e]], 1);
}
__global__ void scan_kernel() {
    __shared__ int part[1024];
    const int T = 1024, ITEMS = (NN + T - 1) / T;
    int tid = threadIdx.x, base = tid * ITEMS, s = 0;
    for (int i = 0; i < ITEMS; ++i) { int idx = base + i; if (idx < NN) s += g_cnt[idx]; }
    part[tid] = s;
    __syncthreads();
    for (int off = 1; off < T; off <<= 1) {
        int v = 0;
        if (tid >= off) v = part[tid - off];
        __syncthreads();
        part[tid] += v;
        __syncthreads();
    }
    int run = (tid == 0) ? 0 : part[tid - 1];
    for (int i = 0; i < ITEMS; ++i) {
        int idx = base + i;
        if (idx < NN) { g_start[idx] = run; g_cursor[idx] = run; run += g_cnt[idx]; }
    }
    if (tid == T - 1) g_start[NN] = part[T - 1];
}
__global__ void fill_kernel(const int* __restrict__ dst) {
    int e = blockIdx.x * 256 + threadIdx.x;
    if (e < EE) { int pos = atomicAdd(&g_cursor[dst[e]], 1); g_eid[pos] = e; }
}
// deterministic order: sort each node's list in a local buffer
__global__ void sort_kernel() {
    int n = blockIdx.x * 128 + threadIdx.x;
    if (n >= NN) return;
    int s0 = g_start[n], s1 = g_start[n + 1];
    int d = s1 - s0;
    if (d <= 1) return;
    if (d <= 96) {
        int buf[96];
        for (int i = 0; i < d; ++i) buf[i] = g_eid[s0 + i];
        for (int i = 1; i < d; ++i) {
            int v = buf[i], j = i - 1;
            while (j >= 0 && buf[j] > v) { buf[j + 1] = buf[j]; --j; }
            buf[j + 1] = v;
        }
        for (int i = 0; i < d; ++i) g_eid[s0 + i] = buf[i];
    } else {
        for (int i = s0 + 1; i < s1; ++i) {
            int v = g_eid[i], j = i - 1;
            while (j >= s0 && g_eid[j] > v) { g_eid[j + 1] = g_eid[j]; --j; }
            g_eid[j + 1] = v;
        }
    }
}
// materialize dst-sorted edge arrays (once); ea pre-packed as duplicated half2
__global__ void gather_kernel(const int* __restrict__ src,
                              const float* __restrict__ eattr) {
    int p = blockIdx.x * 256 + threadIdx.x;
    if (p >= EE) return;
    int e = g_eid[p];
    g_srcs[p] = src[e];
    const float* s = eattr + (size_t)e * 10;
    __half2* d = g_eah + (size_t)p * 12;
    #pragma unroll
    for (int j = 0; j < 10; ++j) d[j] = __float2half2_rn(s[j]);
    d[10] = __floats2half2_rn(0.f, 0.f);
    d[11] = __floats2half2_rn(0.f, 0.f);
}

// ---------------- edge-matrix chain precompute ----------------
__global__ void chain_kernel(const float* __restrict__ eW, const float* __restrict__ eb,
                             const float* __restrict__ Weu, const float* __restrict__ beu) {
    __shared__ float Ash[10 * 256];
    __shared__ float dsh[256];
    int tid = threadIdx.x;
    for (int t = tid; t < 2560; t += 256) Ash[t] = eW[t];
    dsh[tid] = eb[tid];
    __syncthreads();
    for (int i = 0; i < NLAY; ++i) {
        for (int t = tid; t < 2560; t += 256) g_A[i * 2560 + t] = Ash[t];
        g_d[i * 256 + tid] = dsh[tid];
        __syncthreads();
        if (i == NLAY - 1) break;
        const float* Wp = Weu + (size_t)i * 65536;
        float accA[10];
        #pragma unroll
        for (int k = 0; k < 10; ++k) accA[k] = 0.f;
        float accd = 0.f;
        for (int c = 0; c < 256; ++c) {
            float w = Wp[c * 256 + tid];
            accd = fmaf(dsh[c], w, accd);
            #pragma unroll
            for (int k = 0; k < 10; ++k) accA[k] = fmaf(Ash[k * 256 + c], w, accA[k]);
        }
        accd += beu[i * 256 + tid];
        __syncthreads();
        #pragma unroll
        for (int k = 0; k < 10; ++k) Ash[k * 256 + tid] = accA[k];
        dsh[tid] = accd;
        __syncthreads();
    }
}
__global__ void bmat_kernel(const float* __restrict__ We) {
    __shared__ float Ash[10 * 256];
    __shared__ float dsh[256];
    int i = blockIdx.x, tid = threadIdx.x;
    for (int t = tid; t < 2560; t += 256) Ash[t] = g_A[i * 2560 + t];
    dsh[tid] = g_d[i * 256 + tid];
    __syncthreads();
    const float* Wp = We + (size_t)i * 65536;
    float accB[10];
    #pragma unroll
    for (int k = 0; k < 10; ++k) accB[k] = 0.f;
    float accc = 0.f;
    for (int c = 0; c < 256; ++c) {
        float w = Wp[c * 256 + tid];
        accc = fmaf(dsh[c], w, accc);
        #pragma unroll
        for (int k = 0; k < 10; ++k) accB[k] = fmaf(Ash[k * 256 + c], w, accB[k]);
    }
    #pragma unroll
    for (int k = 0; k < 10; ++k) g_B[i * 2560 + k * 256 + tid] = accB[k];
    g_c[i * 256 + tid] = accc;
}

// ---------------- weight transpose + fp16 split ----------------
__global__ void wprep_kernel(const float* __restrict__ Wl, const float* __restrict__ Wr,
                             const float* __restrict__ oW1) {
    int idx = blockIdx.x * 256 + threadIdx.x;
    const int LTOT = NLAY * 512 * 256;
    float v;
    if (idx < LTOT) {
        int l = idx >> 17;
        int rem = idx & 131071;
        int row = rem >> 8, k = rem & 255;
        v = (row < 256) ? Wl[(size_t)l * 65536 + k * 256 + row]
                        : Wr[(size_t)l * 65536 + k * 256 + (row - 256)];
    } else if (idx < LTOT + 128 * 256) {
        int rem = idx - LTOT;
        int row = rem >> 8, k = rem & 255;
        v = oW1[k * 128 + row];
    } else return;
    __half hi, lo;
    split_f16(v, hi, lo);
    g_WTh[idx] = hi; g_WTl[idx] = lo;
}

// ---------------- node encoder ----------------
__global__ void encoder_kernel(const float* __restrict__ x, const float* __restrict__ nW,
                               const float* __restrict__ nb) {
    int idx = blockIdx.x * 256 + threadIdx.x;
    int n = idx >> 8, c = idx & 255;
    if (n >= NN) return;
    float s = nb[c];
    #pragma unroll
    for (int k = 0; k < 13; ++k) s = fmaf(x[n * 13 + k], nW[k * 256 + c], s);
    __half hi, lo;
    split_f16(s, hi, lo);
    g_hh[0][idx] = hi; g_hl[0][idx] = lo;
}

// ---------------- FP16 mma.sync GEMM (R13 config: BM=128, BN=128, 8 warps) ----------------
// passes==3: hi/lo split (head GEMM); passes==1: AhBh only (layer GEMMs).
#define SA 40
#define ARR_H 5120
#define BUF_H (4 * ARR_H)
#define GSMEM_BYTES (2 * BUF_H * 2)

__global__ __launch_bounds__(256, 2)
void mma_gemm(int hsel, int wrow0, const float* __restrict__ bias0,
              const float* __restrict__ bias1, int outmode, float slope, int passes) {
    extern __shared__ __align__(16) __half sm[];
    const __half* __restrict__ Ah = g_hh[hsel];
    const __half* __restrict__ Al = g_hl[hsel];

    int tid = threadIdx.x;
    int wid = tid >> 5, lane = tid & 31;
    int warp_m = wid & 1, warp_n = wid >> 1;
    int m0 = blockIdx.x * 128;
    int colg = blockIdx.y * 128;
    int tig = lane & 3, grp = lane >> 2;
    const bool lo_on = (passes == 3);

    int arow = (lane & 7) + ((lane >> 3) & 1) * 8;
    int acol = (lane >> 4) * 8;
    int brow = lane & 7;
    int bcol = ((lane >> 3) & 1) * 8;

    float c[4][4][4];
    #pragma unroll
    for (int mi = 0; mi < 4; ++mi)
        #pragma unroll
        for (int ni = 0; ni < 4; ++ni)
            #pragma unroll
            for (int j = 0; j < 4; ++j) c[mi][ni][j] = 0.f;

    auto issue = [&](int kb, int buf) {
        int kt = kb * 32;
        __half* base = sm + buf * BUF_H;
        #pragma unroll
        for (int i = 0; i < 8; ++i) {
            int slot = tid + i * 256;
            int arr = slot >> 9;                  // 0:Ah 1:Al 2:Bh 3:Bl
            if (!lo_on && (arr & 1)) continue;    // 1-pass: skip lo arrays
            int rc = slot & 511;
            int r = rc >> 2, ch = rc & 3;
            const __half* src;
            int bytes = 16;
            if (arr < 2) {
                int gm = m0 + r;
                if (gm >= NN) { gm = NN - 1; bytes = 0; }
                src = (arr == 0 ? Ah : Al) + (size_t)gm * 256 + kt + ch * 8;
            } else {
                int row = wrow0 + colg + r;
                src = (arr == 2 ? g_WTh : g_WTl) + (size_t)row * 256 + kt + ch * 8;
            }
            uint32_t dst = smem_u32(base + arr * ARR_H + r * SA + ch * 8);
            cp16(dst, src, bytes);
        }
        cp_commit();
    };

    issue(0, 0);
    for (int kb = 0; kb < 8; ++kb) {
        if (kb < 7) {
            issue(kb + 1, (kb + 1) & 1);
            asm volatile("cp.async.wait_group 1;" ::: "memory");
        } else {
            asm volatile("cp.async.wait_group 0;" ::: "memory");
        }
        __syncthreads();

        uint32_t sAh = smem_u32(sm + (kb & 1) * BUF_H);
        uint32_t sAl = sAh + ARR_H * 2;
        uint32_t sBh = sAh + 2 * ARR_H * 2;
        uint32_t sBl = sAh + 3 * ARR_H * 2;

        #pragma unroll
        for (int ks = 0; ks < 2; ++ks) {
            int k0 = ks * 16;
            uint32_t bh[4][2], bl[4][2];
            #pragma unroll
            for (int ni = 0; ni < 4; ++ni) {
                uint32_t boff = (uint32_t)((warp_n * 32 + ni * 8 + brow) * SA + k0 + bcol) * 2;
                ldsm_x2(bh[ni], sBh + boff);
                if (lo_on) ldsm_x2(bl[ni], sBl + boff);
            }
            #pragma unroll
            for (int mi = 0; mi < 4; ++mi) {
                uint32_t aoff = (uint32_t)((warp_m * 64 + mi * 16 + arow) * SA + k0 + acol) * 2;
                uint32_t ah[4], al[4];
                ldsm_x4(ah, sAh + aoff);
                if (lo_on) ldsm_x4(al, sAl + aoff);
                #pragma unroll
                for (int ni = 0; ni < 4; ++ni) {
                    mma_f16(c[mi][ni], ah, bh[ni]);
                    if (lo_on) {
                        mma_f16(c[mi][ni], ah, bl[ni]);
                        mma_f16(c[mi][ni], al, bh[ni]);
                    }
                }
            }
        }
        __syncthreads();
    }

    #pragma unroll
    for (int mi = 0; mi < 4; ++mi) {
        #pragma unroll
        for (int ni = 0; ni < 4; ++ni) {
            int gn = colg + warp_n * 32 + ni * 8 + tig * 2;
            int gm = m0 + warp_m * 64 + mi * 16 + grp;
            int gm2 = gm + 8;
            if (outmode) {
                float b0v = bias0[gn], b1v = bias0[gn + 1];
                if (gm < NN) {
                    float v0 = c[mi][ni][0] + b0v; v0 = v0 >= 0.f ? v0 : slope * v0;
                    float v1 = c[mi][ni][1] + b1v; v1 = v1 >= 0.f ? v1 : slope * v1;
                    *(float2*)(g_t + (size_t)gm * 128 + gn) = make_float2(v0, v1);
                }
                if (gm2 < NN) {
                    float v0 = c[mi][ni][2] + b0v; v0 = v0 >= 0.f ? v0 : slope * v0;
                    float v1 = c[mi][ni][3] + b1v; v1 = v1 >= 0.f ? v1 : slope * v1;
                    *(float2*)(g_t + (size_t)gm2 * 128 + gn) = make_float2(v0, v1);
                }
            } else {
                __half* outp; const float* bp; int cc;
                if (gn < 256) { outp = g_xlh; bp = bias0; cc = gn; }
                else          { outp = g_xrh; bp = bias1; cc = gn - 256; }
                float b0v = bp[cc], b1v = bp[cc + 1];
                if (gm < NN) {
                    __half2 hv = __floats2half2_rn(c[mi][ni][0] + b0v, c[mi][ni][1] + b1v);
                    *(__half2*)(outp + (size_t)gm * 256 + cc) = hv;
                }
                if (gm2 < NN) {
                    __half2 hv = __floats2half2_rn(c[mi][ni][2] + b0v, c[mi][ni][3] + b1v);
                    *(__half2*)(outp + (size_t)gm2 * 256 + cc) = hv;
                }
            }
        }
    }
}

// ---------------- fused attention v6b: 2-edge unroll + xr folded into c ----------------
__global__ __launch_bounds__(128)
void attn_fused(int layer, int hin,
                const float* __restrict__ att, const float* __restrict__ conv_b,
                const float* __restrict__ bng, const float* __restrict__ bnb,
                const float* __restrict__ bnrm, const float* __restrict__ bnrv) {
    int tid = threadIdx.x;
    int warp = tid >> 5, lane = tid & 31;
    int n = blockIdx.x * 4 + warp;
    if (n >= NN) return;
    int hout = hin ^ 1;
    int c0 = lane * 8;

    const __half2 zero2 = __floats2half2_rn(0.f, 0.f);
    const __half2 fifth2 = __floats2half2_rn(0.2f, 0.2f);

    __half2 Brg2[10][4];
    #pragma unroll
    for (int k = 0; k < 10; ++k) {
        float4 b0 = *(const float4*)(g_B + layer * 2560 + k * 256 + c0);
        float4 b1 = *(const float4*)(g_B + layer * 2560 + k * 256 + c0 + 4);
        Brg2[k][0] = __floats2half2_rn(b0.x, b0.y);
        Brg2[k][1] = __floats2half2_rn(b0.z, b0.w);
        Brg2[k][2] = __floats2half2_rn(b1.x, b1.y);
        Brg2[k][3] = __floats2half2_rn(b1.z, b1.w);
    }
    __half2 attr2[4], crx2[4];
    {
        float4 a0 = *(const float4*)(att + layer * 256 + c0);
        float4 a1 = *(const float4*)(att + layer * 256 + c0 + 4);
        attr2[0] = __floats2half2_rn(a0.x, a0.y);
        attr2[1] = __floats2half2_rn(a0.z, a0.w);
        attr2[2] = __floats2half2_rn(a1.x, a1.y);
        attr2[3] = __floats2half2_rn(a1.z, a1.w);
        float4 d0 = *(const float4*)(g_c + layer * 256 + c0);
        float4 d1 = *(const float4*)(g_c + layer * 256 + c0 + 4);
        uint4 rv4 = *(const uint4*)(g_xrh + (size_t)n * 256 + c0);
        // crx = c + xr (both loop-invariant for this node)
        crx2[0] = __hadd2(__floats2half2_rn(d0.x, d0.y), *(__half2*)&rv4.x);
        crx2[1] = __hadd2(__floats2half2_rn(d0.z, d0.w), *(__half2*)&rv4.y);
        crx2[2] = __hadd2(__floats2half2_rn(d1.x, d1.y), *(__half2*)&rv4.z);
        crx2[3] = __hadd2(__floats2half2_rn(d1.z, d1.w), *(__half2*)&rv4.w);
    }

    float accv[8];
    #pragma unroll
    for (int j = 0; j < 8; ++j) accv[j] = 0.f;
    float den = 0.f;

    int s0 = g_start[n], s1 = g_start[n + 1];
    int p = s0;

    // ---- main loop: two independent edges per iteration ----
    for (; p + 1 < s1; p += 2) {
        int snA = g_srcs[p], snB = g_srcs[p + 1];
        uint4 xvA = *(const uint4*)(g_xlh + (size_t)snA * 256 + c0);
        uint4 xvB = *(const uint4*)(g_xlh + (size_t)snB * 256 + c0);
        __half2 xlA[4], xlB[4];
        xlA[0] = *(__half2*)&xvA.x; xlA[1] = *(__half2*)&xvA.y;
        xlA[2] = *(__half2*)&xvA.z; xlA[3] = *(__half2*)&xvA.w;
        xlB[0] = *(__half2*)&xvB.x; xlB[1] = *(__half2*)&xvB.y;
        xlB[2] = *(__half2*)&xvB.z; xlB[3] = *(__half2*)&xvB.w;

        const uint4* eaA4 = (const uint4*)(g_eah + (size_t)p * 12);
        const uint4* eaB4 = (const uint4*)(g_eah + (size_t)(p + 1) * 12);
        uint4 ua0 = eaA4[0], ua1 = eaA4[1], ua2 = eaA4[2];
        uint4 ub0 = eaB4[0], ub1 = eaB4[1], ub2 = eaB4[2];
        __half2 eaA[10], eaB[10];
        eaA[0] = *(__half2*)&ua0.x; eaA[1] = *(__half2*)&ua0.y;
        eaA[2] = *(__half2*)&ua0.z; eaA[3] = *(__half2*)&ua0.w;
        eaA[4] = *(__half2*)&ua1.x; eaA[5] = *(__half2*)&ua1.y;
        eaA[6] = *(__half2*)&ua1.z; eaA[7] = *(__half2*)&ua1.w;
        eaA[8] = *(__half2*)&ua2.x; eaA[9] = *(__half2*)&ua2.y;
        eaB[0] = *(__half2*)&ub0.x; eaB[1] = *(__half2*)&ub0.y;
        eaB[2] = *(__half2*)&ub0.z; eaB[3] = *(__half2*)&ub0.w;
        eaB[4] = *(__half2*)&ub1.x; eaB[5] = *(__half2*)&ub1.y;
        eaB[6] = *(__half2*)&ub1.z; eaB[7] = *(__half2*)&ub1.w;
        eaB[8] = *(__half2*)&ub2.x; eaB[9] = *(__half2*)&ub2.y;

        __half2 mA[4] = {crx2[0], crx2[1], crx2[2], crx2[3]};
        __half2 mB[4] = {crx2[0], crx2[1], crx2[2], crx2[3]};
        #pragma unroll
        for (int k = 0; k < 10; ++k) {
            #pragma unroll
            for (int j2 = 0; j2 < 4; ++j2) {
                mA[j2] = __hfma2(eaA[k], Brg2[k][j2], mA[j2]);
                mB[j2] = __hfma2(eaB[k], Brg2[k][j2], mB[j2]);
            }
        }

        __half2 sA2 = zero2, sB2 = zero2;
        #pragma unroll
        for (int j2 = 0; j2 < 4; ++j2) {
            __half2 vA = __hadd2(mA[j2], xlA[j2]);
            __half2 lkA = __hfma2(__hmin2(vA, zero2), fifth2, __hmax2(vA, zero2));
            sA2 = __hfma2(lkA, attr2[j2], sA2);
            __half2 vB = __hadd2(mB[j2], xlB[j2]);
            __half2 lkB = __hfma2(__hmin2(vB, zero2), fifth2, __hmax2(vB, zero2));
            sB2 = __hfma2(lkB, attr2[j2], sB2);
        }
        float2 sfA = __half22float2(sA2);
        float2 sfB = __half22float2(sB2);
        float sA = sfA.x + sfA.y;
        float sB = sfB.x + sfB.y;
        sA += __shfl_xor_sync(0xffffffffu, sA, 1);
        sB += __shfl_xor_sync(0xffffffffu, sB, 1);
        sA += __shfl_xor_sync(0xffffffffu, sA, 2);
        sB += __shfl_xor_sync(0xffffffffu, sB, 2);
        float wA = __expf(sA);
        float wB = __expf(sB);
        den += wA + wB;
        #pragma unroll
        for (int j2 = 0; j2 < 4; ++j2) {
            float2 xfA = __half22float2(xlA[j2]);
            float2 xfB = __half22float2(xlB[j2]);
            accv[2 * j2]     = fmaf(wA, xfA.x, fmaf(wB, xfB.x, accv[2 * j2]));
            accv[2 * j2 + 1] = fmaf(wA, xfA.y, fmaf(wB, xfB.y, accv[2 * j2 + 1]));
        }
    }

    // ---- tail edge ----
    if (p < s1) {
        int sn = g_srcs[p];
        uint4 xv = *(const uint4*)(g_xlh + (size_t)sn * 256 + c0);
        __half2 xl2[4];
        xl2[0] = *(__half2*)&xv.x; xl2[1] = *(__half2*)&xv.y;
        xl2[2] = *(__half2*)&xv.z; xl2[3] = *(__half2*)&xv.w;
        const uint4* ea4 = (const uint4*)(g_eah + (size_t)p * 12);
        uint4 u0 = ea4[0], u1 = ea4[1], u2 = ea4[2];
        __half2 ea[10];
        ea[0] = *(__half2*)&u0.x; ea[1] = *(__half2*)&u0.y;
        ea[2] = *(__half2*)&u0.z; ea[3] = *(__half2*)&u0.w;
        ea[4] = *(__half2*)&u1.x; ea[5] = *(__half2*)&u1.y;
        ea[6] = *(__half2*)&u1.z; ea[7] = *(__half2*)&u1.w;
        ea[8] = *(__half2*)&u2.x; ea[9] = *(__half2*)&u2.y;

        __half2 m2[4] = {crx2[0], crx2[1], crx2[2], crx2[3]};
        #pragma unroll
        for (int k = 0; k < 10; ++k)
            #pragma unroll
            for (int j2 = 0; j2 < 4; ++j2)
                m2[j2] = __hfma2(ea[k], Brg2[k][j2], m2[j2]);

        __half2 s2 = zero2;
        #pragma unroll
        for (int j2 = 0; j2 < 4; ++j2) {
            __half2 v2 = __hadd2(m2[j2], xl2[j2]);
            __half2 lk = __hfma2(__hmin2(v2, zero2), fifth2, __hmax2(v2, zero2));
            s2 = __hfma2(lk, attr2[j2], s2);
        }
        float2 sf = __half22float2(s2);
        float s = sf.x + sf.y;
        s += __shfl_xor_sync(0xffffffffu, s, 1);
        s += __shfl_xor_sync(0xffffffffu, s, 2);
        float w = __expf(s);
        den += w;
        #pragma unroll
        for (int j2 = 0; j2 < 4; ++j2) {
            float2 xf = __half22float2(xl2[j2]);
            accv[2 * j2]     = fmaf(w, xf.x, accv[2 * j2]);
            accv[2 * j2 + 1] = fmaf(w, xf.y, accv[2 * j2 + 1]);
        }
    }

    float invden = 1.f / (den + 1e-16f);

    float4 cb0 = *(const float4*)(conv_b + layer * 256 + c0);
    float4 cb1 = *(const float4*)(conv_b + layer * 256 + c0 + 4);
    float4 g0  = *(const float4*)(bng + layer * 256 + c0);
    float4 g1  = *(const float4*)(bng + layer * 256 + c0 + 4);
    float4 bb0 = *(const float4*)(bnb + layer * 256 + c0);
    float4 bb1 = *(const float4*)(bnb + layer * 256 + c0 + 4);
    float4 rm0 = *(const float4*)(bnrm + layer * 256 + c0);
    float4 rm1 = *(const float4*)(bnrm + layer * 256 + c0 + 4);
    float4 rv0 = *(const float4*)(bnrv + layer * 256 + c0);
    float4 rv1 = *(const float4*)(bnrv + layer * 256 + c0 + 4);
    float cb[8] = {cb0.x, cb0.y, cb0.z, cb0.w, cb1.x, cb1.y, cb1.z, cb1.w};
    float gg[8] = {g0.x, g0.y, g0.z, g0.w, g1.x, g1.y, g1.z, g1.w};
    float bbv[8] = {bb0.x, bb0.y, bb0.z, bb0.w, bb1.x, bb1.y, bb1.z, bb1.w};
    float rm[8] = {rm0.x, rm0.y, rm0.z, rm0.w, rm1.x, rm1.y, rm1.z, rm1.w};
    float rv[8] = {rv0.x, rv0.y, rv0.z, rv0.w, rv1.x, rv1.y, rv1.z, rv1.w};

    size_t base = (size_t)n * 256 + c0;
    __half resh[8], resl[8];
    if (layer >= 1) {
        *(uint4*)resh = *(const uint4*)(&g_hh[hin][base]);
        *(uint4*)resl = *(const uint4*)(&g_hl[hin][base]);
    }
    __half oh[8], ol[8];
    #pragma unroll
    for (int j = 0; j < 8; ++j) {
        float sc = gg[j] * rsqrtf(rv[j] + 1e-5f);
        float sh = bbv[j] - rm[j] * sc;
        float v = accv[j] * invden + cb[j];
        v = v * sc + sh;
        v = v >= 0.f ? v : 0.01f * v;
        if (layer >= 1) v += __half2float(resh[j]) + __half2float(resl[j]);
        split_f16(v, oh[j], ol[j]);
    }
    *(uint4*)(&g_hh[hout][base]) = *(const uint4*)oh;
    *(uint4*)(&g_hl[hout][base]) = *(const uint4*)ol;
}

// ---------------- head: out = t @ W2 + b2 ----------------
__global__ void head2_kernel(const float* __restrict__ W2, const float* __restrict__ b2,
                             float* __restrict__ out) {
    __shared__ float w[128];
    int tid = threadIdx.x;
    if (tid < 128) w[tid] = W2[tid];
    __syncthreads();
    int n = blockIdx.x * 256 + tid;
    if (n >= NN) return;
    float s = b2[0];
    const float* tp = g_t + (size_t)n * 128;
    #pragma unroll
    for (int j = 0; j < 128; ++j) s = fmaf(tp[j], w[j], s);
    out[n] = s;
}

// ---------------- launch ----------------
extern "C" void kernel_launch(void* const* d_in, const int* in_sizes, int n_in,
                              void* d_out, int out_size) {
    const float* x      = (const float*)d_in[0];
    const int*   ei     = (const int*)d_in[1];
    const float* eattr  = (const float*)d_in[2];
    const float* nW     = (const float*)d_in[3];
    const float* nb     = (const float*)d_in[4];
    const float* eW     = (const float*)d_in[5];
    const float* eb     = (const float*)d_in[6];
    const float* Wl     = (const float*)d_in[7];
    const float* bl     = (const float*)d_in[8];
    const float* Wr     = (const float*)d_in[9];
    const float* br     = (const float*)d_in[10];
    const float* We     = (const float*)d_in[11];
    const float* att    = (const float*)d_in[12];
    const float* conv_b = (const float*)d_in[13];
    const float* Weu    = (const float*)d_in[14];
    const float* beu    = (const float*)d_in[15];
    const float* bng    = (const float*)d_in[16];
    const float* bnb    = (const float*)d_in[17];
    const float* bnrm   = (const float*)d_in[18];
    const float* bnrv   = (const float*)d_in[19];
    const float* oW1    = (const float*)d_in[20];
    const float* ob1    = (const float*)d_in[21];
    const float* oW2    = (const float*)d_in[22];
    const float* ob2    = (const float*)d_in[23];

    const int* srcp = ei;
    const int* dstp = ei + EE;

    static int attr_set = 0;
    if (!attr_set) {
        cudaFuncSetAttribute(mma_gemm, cudaFuncAttributeMaxDynamicSharedMemorySize,
                             GSMEM_BYTES);
        attr_set = 1;
    }

    const int MT = (NN + 127) / 128;   // 235
    dim3 gemm_grid(MT, 4);
    dim3 head_grid(MT, 1);

    // --- mma_gemm L0 in the ncu capture slot (4th launch) ---
    wprep_kernel<<<3200, 256>>>(Wl, Wr, oW1);                     // 1
    encoder_kernel<<<NN, 256>>>(x, nW, nb);                       // 2
    zero_kernel<<<(NN + 256) / 256, 256>>>();                     // 3
    mma_gemm<<<gemm_grid, 256, GSMEM_BYTES>>>(0, 0, bl, br, 0, 1.0f, 1);  // 4 <- profiled

    // CSR build (deterministic) + sorted edge arrays
    count_kernel<<<(EE + 255) / 256, 256>>>(dstp);
    scan_kernel<<<1, 1024>>>();
    fill_kernel<<<(EE + 255) / 256, 256>>>(dstp);
    sort_kernel<<<(NN + 127) / 128, 128>>>();
    gather_kernel<<<(EE + 255) / 256, 256>>>(srcp, eattr);

    // edge matrix chain
    chain_kernel<<<1, 256>>>(eW, eb, Weu, beu);
    bmat_kernel<<<NLAY, 256>>>(We);

    int cur = 0;
    // layer 0 attention (GEMM L0 already issued above)
    attn_fused<<<(NN + 3) / 4, 128>>>(0, cur, att, conv_b, bng, bnb, bnrm, bnrv);
    cur ^= 1;
    for (int i = 1; i < NLAY; ++i) {
        mma_gemm<<<gemm_grid, 256, GSMEM_BYTES>>>(cur, i * 512, bl + i * 256, br + i * 256,
                                                  /*outmode=*/0, /*slope=*/1.0f, /*passes=*/1);
        attn_fused<<<(NN + 3) / 4, 128>>>(i, cur, att, conv_b, bng, bnb, bnrm, bnrv);
        cur ^= 1;
    }

    // output head (fp32-grade 3-pass)
    mma_gemm<<<head_grid, 256, GSMEM_BYTES>>>(cur, NLAY * 512, ob1, (const float*)0,
                                              /*outmode=*/1, /*slope=*/0.01f, /*passes=*/3);
    head2_kernel<<<(NN + 255) / 256, 256>>>(oW2, ob2, (float*)d_out);
}

// round 17
// speedup vs baseline: 1.1645x; 1.0172x over previous
#include <cuda_runtime.h>
#include <cuda_fp16.h>
#include <math.h>
#include <stdint.h>

#define NN    30000
#define EE    480000
#define HIDN  256
#define NLAY  6

// ---------------- static device scratch ----------------
static __device__ __align__(128) __half g_hh[2][NN * HIDN];   // h split hi (fp16)
static __device__ __align__(128) __half g_hl[2][NN * HIDN];   // h split lo (fp16)
static __device__ __align__(128) __half g_xlh[NN * HIDN];     // xl (fp16, attention-only)
static __device__ __align__(128) __half g_xrh[NN * HIDN];     // xr (fp16, attention-only)
static __device__ __align__(128) float  g_t[NN * 128];
static __device__ __align__(128) __half g_WTh[(NLAY * 512 + 128) * 256];
static __device__ __align__(128) __half g_WTl[(NLAY * 512 + 128) * 256];
static __device__ __align__(128) float  g_B[NLAY * 10 * 256];
static __device__ __align__(128) float  g_c[NLAY * 256];
static __device__ __align__(128) float  g_A[NLAY * 10 * 256];
static __device__ __align__(128) float  g_d[NLAY * 256];
static __device__ int g_cnt[NN + 1];
static __device__ int g_start[NN + 1];
static __device__ int g_cursor[NN + 1];
static __device__ int g_eid[EE];
// dst-sorted edge data (built once)
static __device__ __align__(128) int     g_srcs[EE];
static __device__ __align__(128) __half2 g_eah[EE * 12];   // duplicated half2, padded to 48B/edge

// ---------------- helpers ----------------
__device__ __forceinline__ void split_f16(float x, __half& hi, __half& lo) {
    hi = __float2half_rn(x);
    lo = __float2half_rn(x - __half2float(hi));
}

__device__ __forceinline__ uint32_t smem_u32(const void* p) {
    uint32_t a;
    asm("{ .reg .u64 t; cvta.to.shared.u64 t, %1; cvt.u32.u64 %0, t; }" : "=r"(a) : "l"(p));
    return a;
}

__device__ __forceinline__ void cp16(uint32_t dst, const void* src, int bytes) {
    asm volatile("cp.async.cg.shared.global [%0], [%1], 16, %2;"
                 :: "r"(dst), "l"(src), "r"(bytes));
}
__device__ __forceinline__ void cp_commit() {
    asm volatile("cp.async.commit_group;" ::: "memory");
}

__device__ __forceinline__ void mma_f16(float* d, const uint32_t* a, const uint32_t* b) {
    asm volatile(
        "mma.sync.aligned.m16n8k16.row.col.f32.f16.f16.f32 "
        "{%0,%1,%2,%3}, {%4,%5,%6,%7}, {%8,%9}, {%0,%1,%2,%3};"
        : "+f"(d[0]), "+f"(d[1]), "+f"(d[2]), "+f"(d[3])
        : "r"(a[0]), "r"(a[1]), "r"(a[2]), "r"(a[3]), "r"(b[0]), "r"(b[1]));
}

__device__ __forceinline__ void ldsm_x4(uint32_t* r, uint32_t addr) {
    asm volatile("ldmatrix.sync.aligned.m8n8.x4.shared.b16 {%0,%1,%2,%3}, [%4];"
                 : "=r"(r[0]), "=r"(r[1]), "=r"(r[2]), "=r"(r[3]) : "r"(addr));
}
__device__ __forceinline__ void ldsm_x2(uint32_t* r, uint32_t addr) {
    asm volatile("ldmatrix.sync.aligned.m8n8.x2.shared.b16 {%0,%1}, [%2];"
                 : "=r"(r[0]), "=r"(r[1]) : "r"(addr));
}

// ---------------- CSR build ----------------
__global__ void zero_kernel() {
    int i = blockIdx.x * 256 + threadIdx.x;
    if (i <= NN) g_cnt[i] = 0;
}
__global__ void count_kernel(const int* __restrict__ dst) {
    int e = blockIdx.x * 256 + threadIdx.x;
    if (e < EE) atomicAdd(&g_cnt[dst[e]], 1);
}
__global__ void scan_kernel() {
    __shared__ int part[1024];
    const int T = 1024, ITEMS = (NN + T - 1) / T;
    int tid = threadIdx.x, base = tid * ITEMS, s = 0;
    for (int i = 0; i < ITEMS; ++i) { int idx = base + i; if (idx < NN) s += g_cnt[idx]; }
    part[tid] = s;
    __syncthreads();
    for (int off = 1; off < T; off <<= 1) {
        int v = 0;
        if (tid >= off) v = part[tid - off];
        __syncthreads();
        part[tid] += v;
        __syncthreads();
    }
    int run = (tid == 0) ? 0 : part[tid - 1];
    for (int i = 0; i < ITEMS; ++i) {
        int idx = base + i;
        if (idx < NN) { g_start[idx] = run; g_cursor[idx] = run; run += g_cnt[idx]; }
    }
    if (tid == T - 1) g_start[NN] = part[T - 1];
}
__global__ void fill_kernel(const int* __restrict__ dst) {
    int e = blockIdx.x * 256 + threadIdx.x;
    if (e < EE) { int pos = atomicAdd(&g_cursor[dst[e]], 1); g_eid[pos] = e; }
}
// deterministic order: sort each node's list in a local buffer
__global__ void sort_kernel() {
    int n = blockIdx.x * 128 + threadIdx.x;
    if (n >= NN) return;
    int s0 = g_start[n], s1 = g_start[n + 1];
    int d = s1 - s0;
    if (d <= 1) return;
    if (d <= 96) {
        int buf[96];
        for (int i = 0; i < d; ++i) buf[i] = g_eid[s0 + i];
        for (int i = 1; i < d; ++i) {
            int v = buf[i], j = i - 1;
            while (j >= 0 && buf[j] > v) { buf[j + 1] = buf[j]; --j; }
            buf[j + 1] = v;
        }
        for (int i = 0; i < d; ++i) g_eid[s0 + i] = buf[i];
    } else {
        for (int i = s0 + 1; i < s1; ++i) {
            int v = g_eid[i], j = i - 1;
            while (j >= s0 && g_eid[j] > v) { g_eid[j + 1] = g_eid[j]; --j; }
            g_eid[j + 1] = v;
        }
    }
}
// materialize dst-sorted edge arrays (once); ea pre-packed as duplicated half2
__global__ void gather_kernel(const int* __restrict__ src,
                              const float* __restrict__ eattr) {
    int p = blockIdx.x * 256 + threadIdx.x;
    if (p >= EE) return;
    int e = g_eid[p];
    g_srcs[p] = src[e];
    const float* s = eattr + (size_t)e * 10;
    __half2* d = g_eah + (size_t)p * 12;
    #pragma unroll
    for (int j = 0; j < 10; ++j) d[j] = __float2half2_rn(s[j]);
    d[10] = __floats2half2_rn(0.f, 0.f);
    d[11] = __floats2half2_rn(0.f, 0.f);
}

// ---------------- edge-matrix chain precompute ----------------
__global__ void chain_kernel(const float* __restrict__ eW, const float* __restrict__ eb,
                             const float* __restrict__ Weu, const float* __restrict__ beu) {
    __shared__ float Ash[10 * 256];
    __shared__ float dsh[256];
    int tid = threadIdx.x;
    for (int t = tid; t < 2560; t += 256) Ash[t] = eW[t];
    dsh[tid] = eb[tid];
    __syncthreads();
    for (int i = 0; i < NLAY; ++i) {
        for (int t = tid; t < 2560; t += 256) g_A[i * 2560 + t] = Ash[t];
        g_d[i * 256 + tid] = dsh[tid];
        __syncthreads();
        if (i == NLAY - 1) break;
        const float* Wp = Weu + (size_t)i * 65536;
        float accA[10];
        #pragma unroll
        for (int k = 0; k < 10; ++k) accA[k] = 0.f;
        float accd = 0.f;
        for (int c = 0; c < 256; ++c) {
            float w = Wp[c * 256 + tid];
            accd = fmaf(dsh[c], w, accd);
            #pragma unroll
            for (int k = 0; k < 10; ++k) accA[k] = fmaf(Ash[k * 256 + c], w, accA[k]);
        }
        accd += beu[i * 256 + tid];
        __syncthreads();
        #pragma unroll
        for (int k = 0; k < 10; ++k) Ash[k * 256 + tid] = accA[k];
        dsh[tid] = accd;
        __syncthreads();
    }
}
__global__ void bmat_kernel(const float* __restrict__ We) {
    __shared__ float Ash[10 * 256];
    __shared__ float dsh[256];
    int i = blockIdx.x, tid = threadIdx.x;
    for (int t = tid; t < 2560; t += 256) Ash[t] = g_A[i * 2560 + t];
    dsh[tid] = g_d[i * 256 + tid];
    __syncthreads();
    const float* Wp = We + (size_t)i * 65536;
    float accB[10];
    #pragma unroll
    for (int k = 0; k < 10; ++k) accB[k] = 0.f;
    float accc = 0.f;
    for (int c = 0; c < 256; ++c) {
        float w = Wp[c * 256 + tid];
        accc = fmaf(dsh[c], w, accc);
        #pragma unroll
        for (int k = 0; k < 10; ++k) accB[k] = fmaf(Ash[k * 256 + c], w, accB[k]);
    }
    #pragma unroll
    for (int k = 0; k < 10; ++k) g_B[i * 2560 + k * 256 + tid] = accB[k];
    g_c[i * 256 + tid] = accc;
}

// ---------------- weight transpose + fp16 split ----------------
__global__ void wprep_kernel(const float* __restrict__ Wl, const float* __restrict__ Wr,
                             const float* __restrict__ oW1) {
    int idx = blockIdx.x * 256 + threadIdx.x;
    const int LTOT = NLAY * 512 * 256;
    float v;
    if (idx < LTOT) {
        int l = idx >> 17;
        int rem = idx & 131071;
        int row = rem >> 8, k = rem & 255;
        v = (row < 256) ? Wl[(size_t)l * 65536 + k * 256 + row]
                        : Wr[(size_t)l * 65536 + k * 256 + (row - 256)];
    } else if (idx < LTOT + 128 * 256) {
        int rem = idx - LTOT;
        int row = rem >> 8, k = rem & 255;
        v = oW1[k * 128 + row];
    } else return;
    __half hi, lo;
    split_f16(v, hi, lo);
    g_WTh[idx] = hi; g_WTl[idx] = lo;
}

// ---------------- node encoder ----------------
__global__ void encoder_kernel(const float* __restrict__ x, const float* __restrict__ nW,
                               const float* __restrict__ nb) {
    int idx = blockIdx.x * 256 + threadIdx.x;
    int n = idx >> 8, c = idx & 255;
    if (n >= NN) return;
    float s = nb[c];
    #pragma unroll
    for (int k = 0; k < 13; ++k) s = fmaf(x[n * 13 + k], nW[k * 256 + c], s);
    __half hi, lo;
    split_f16(s, hi, lo);
    g_hh[0][idx] = hi; g_hl[0][idx] = lo;
}

// ---------------- FP16 mma.sync GEMM (R13 config: BM=128, BN=128, 8 warps) ----------------
// passes==3: hi/lo split (head GEMM); passes==1: AhBh only (layer GEMMs).
#define SA 40
#define ARR_H 5120
#define BUF_H (4 * ARR_H)
#define GSMEM_BYTES (2 * BUF_H * 2)

__global__ __launch_bounds__(256, 2)
void mma_gemm(int hsel, int wrow0, const float* __restrict__ bias0,
              const float* __restrict__ bias1, int outmode, float slope, int passes) {
    extern __shared__ __align__(16) __half sm[];
    const __half* __restrict__ Ah = g_hh[hsel];
    const __half* __restrict__ Al = g_hl[hsel];

    int tid = threadIdx.x;
    int wid = tid >> 5, lane = tid & 31;
    int warp_m = wid & 1, warp_n = wid >> 1;
    int m0 = blockIdx.x * 128;
    int colg = blockIdx.y * 128;
    int tig = lane & 3, grp = lane >> 2;
    const bool lo_on = (passes == 3);

    int arow = (lane & 7) + ((lane >> 3) & 1) * 8;
    int acol = (lane >> 4) * 8;
    int brow = lane & 7;
    int bcol = ((lane >> 3) & 1) * 8;

    float c[4][4][4];
    #pragma unroll
    for (int mi = 0; mi < 4; ++mi)
        #pragma unroll
        for (int ni = 0; ni < 4; ++ni)
            #pragma unroll
            for (int j = 0; j < 4; ++j) c[mi][ni][j] = 0.f;

    auto issue = [&](int kb, int buf) {
        int kt = kb * 32;
        __half* base = sm + buf * BUF_H;
        #pragma unroll
        for (int i = 0; i < 8; ++i) {
            int slot = tid + i * 256;
            int arr = slot >> 9;                  // 0:Ah 1:Al 2:Bh 3:Bl
            if (!lo_on && (arr & 1)) continue;    // 1-pass: skip lo arrays
            int rc = slot & 511;
            int r = rc >> 2, ch = rc & 3;
            const __half* src;
            int bytes = 16;
            if (arr < 2) {
                int gm = m0 + r;
                if (gm >= NN) { gm = NN - 1; bytes = 0; }
                src = (arr == 0 ? Ah : Al) + (size_t)gm * 256 + kt + ch * 8;
            } else {
                int row = wrow0 + colg + r;
                src = (arr == 2 ? g_WTh : g_WTl) + (size_t)row * 256 + kt + ch * 8;
            }
            uint32_t dst = smem_u32(base + arr * ARR_H + r * SA + ch * 8);
            cp16(dst, src, bytes);
        }
        cp_commit();
    };

    issue(0, 0);
    for (int kb = 0; kb < 8; ++kb) {
        if (kb < 7) {
            issue(kb + 1, (kb + 1) & 1);
            asm volatile("cp.async.wait_group 1;" ::: "memory");
        } else {
            asm volatile("cp.async.wait_group 0;" ::: "memory");
        }
        __syncthreads();

        uint32_t sAh = smem_u32(sm + (kb & 1) * BUF_H);
        uint32_t sAl = sAh + ARR_H * 2;
        uint32_t sBh = sAh + 2 * ARR_H * 2;
        uint32_t sBl = sAh + 3 * ARR_H * 2;

        #pragma unroll
        for (int ks = 0; ks < 2; ++ks) {
            int k0 = ks * 16;
            uint32_t bh[4][2], bl[4][2];
            #pragma unroll
            for (int ni = 0; ni < 4; ++ni) {
                uint32_t boff = (uint32_t)((warp_n * 32 + ni * 8 + brow) * SA + k0 + bcol) * 2;
                ldsm_x2(bh[ni], sBh + boff);
                if (lo_on) ldsm_x2(bl[ni], sBl + boff);
            }
            #pragma unroll
            for (int mi = 0; mi < 4; ++mi) {
                uint32_t aoff = (uint32_t)((warp_m * 64 + mi * 16 + arow) * SA + k0 + acol) * 2;
                uint32_t ah[4], al[4];
                ldsm_x4(ah, sAh + aoff);
                if (lo_on) ldsm_x4(al, sAl + aoff);
                #pragma unroll
                for (int ni = 0; ni < 4; ++ni) {
                    mma_f16(c[mi][ni], ah, bh[ni]);
                    if (lo_on) {
                        mma_f16(c[mi][ni], ah, bl[ni]);
                        mma_f16(c[mi][ni], al, bh[ni]);
                    }
                }
            }
        }
        __syncthreads();
    }

    #pragma unroll
    for (int mi = 0; mi < 4; ++mi) {
        #pragma unroll
        for (int ni = 0; ni < 4; ++ni) {
            int gn = colg + warp_n * 32 + ni * 8 + tig * 2;
            int gm = m0 + warp_m * 64 + mi * 16 + grp;
            int gm2 = gm + 8;
            if (outmode) {
                float b0v = bias0[gn], b1v = bias0[gn + 1];
                if (gm < NN) {
                    float v0 = c[mi][ni][0] + b0v; v0 = v0 >= 0.f ? v0 : slope * v0;
                    float v1 = c[mi][ni][1] + b1v; v1 = v1 >= 0.f ? v1 : slope * v1;
                    *(float2*)(g_t + (size_t)gm * 128 + gn) = make_float2(v0, v1);
                }
                if (gm2 < NN) {
                    float v0 = c[mi][ni][2] + b0v; v0 = v0 >= 0.f ? v0 : slope * v0;
                    float v1 = c[mi][ni][3] + b1v; v1 = v1 >= 0.f ? v1 : slope * v1;
                    *(float2*)(g_t + (size_t)gm2 * 128 + gn) = make_float2(v0, v1);
                }
            } else {
                __half* outp; const float* bp; int cc;
                if (gn < 256) { outp = g_xlh; bp = bias0; cc = gn; }
                else          { outp = g_xrh; bp = bias1; cc = gn - 256; }
                float b0v = bp[cc], b1v = bp[cc + 1];
                if (gm < NN) {
                    __half2 hv = __floats2half2_rn(c[mi][ni][0] + b0v, c[mi][ni][1] + b1v);
                    *(__half2*)(outp + (size_t)gm * 256 + cc) = hv;
                }
                if (gm2 < NN) {
                    __half2 hv = __floats2half2_rn(c[mi][ni][2] + b0v, c[mi][ni][3] + b1v);
                    *(__half2*)(outp + (size_t)gm2 * 256 + cc) = hv;
                }
            }
        }
    }
}

// ---------------- fused attention v6b: 2-edge unroll + xr folded into c ----------------
__global__ __launch_bounds__(128)
void attn_fused(int layer, int hin,
                const float* __restrict__ att, const float* __restrict__ conv_b,
                const float* __restrict__ bng, const float* __restrict__ bnb,
                const float* __restrict__ bnrm, const float* __restrict__ bnrv) {
    int tid = threadIdx.x;
    int warp = tid >> 5, lane = tid & 31;
    int n = blockIdx.x * 4 + warp;
    if (n >= NN) return;
    int hout = hin ^ 1;
    int c0 = lane * 8;

    const __half2 zero2 = __floats2half2_rn(0.f, 0.f);
    const __half2 fifth2 = __floats2half2_rn(0.2f, 0.2f);

    __half2 Brg2[10][4];
    #pragma unroll
    for (int k = 0; k < 10; ++k) {
        float4 b0 = *(const float4*)(g_B + layer * 2560 + k * 256 + c0);
        float4 b1 = *(const float4*)(g_B + layer * 2560 + k * 256 + c0 + 4);
        Brg2[k][0] = __floats2half2_rn(b0.x, b0.y);
        Brg2[k][1] = __floats2half2_rn(b0.z, b0.w);
        Brg2[k][2] = __floats2half2_rn(b1.x, b1.y);
        Brg2[k][3] = __floats2half2_rn(b1.z, b1.w);
    }
    __half2 attr2[4], crx2[4];
    {
        float4 a0 = *(const float4*)(att + layer * 256 + c0);
        float4 a1 = *(const float4*)(att + layer * 256 + c0 + 4);
        attr2[0] = __floats2half2_rn(a0.x, a0.y);
        attr2[1] = __floats2half2_rn(a0.z, a0.w);
        attr2[2] = __floats2half2_rn(a1.x, a1.y);
        attr2[3] = __floats2half2_rn(a1.z, a1.w);
        float4 d0 = *(const float4*)(g_c + layer * 256 + c0);
        float4 d1 = *(const float4*)(g_c + layer * 256 + c0 + 4);
        uint4 rv4 = *(const uint4*)(g_xrh + (size_t)n * 256 + c0);
        crx2[0] = __hadd2(__floats2half2_rn(d0.x, d0.y), *(__half2*)&rv4.x);
        crx2[1] = __hadd2(__floats2half2_rn(d0.z, d0.w), *(__half2*)&rv4.y);
        crx2[2] = __hadd2(__floats2half2_rn(d1.x, d1.y), *(__half2*)&rv4.z);
        crx2[3] = __hadd2(__floats2half2_rn(d1.z, d1.w), *(__half2*)&rv4.w);
    }

    float accv[8];
    #pragma unroll
    for (int j = 0; j < 8; ++j) accv[j] = 0.f;
    float den = 0.f;

    int s0 = g_start[n], s1 = g_start[n + 1];
    int p = s0;

    // ---- main loop: two independent edges per iteration ----
    for (; p + 1 < s1; p += 2) {
        int snA = g_srcs[p], snB = g_srcs[p + 1];
        uint4 xvA = *(const uint4*)(g_xlh + (size_t)snA * 256 + c0);
        uint4 xvB = *(const uint4*)(g_xlh + (size_t)snB * 256 + c0);
        __half2 xlA[4], xlB[4];
        xlA[0] = *(__half2*)&xvA.x; xlA[1] = *(__half2*)&xvA.y;
        xlA[2] = *(__half2*)&xvA.z; xlA[3] = *(__half2*)&xvA.w;
        xlB[0] = *(__half2*)&xvB.x; xlB[1] = *(__half2*)&xvB.y;
        xlB[2] = *(__half2*)&xvB.z; xlB[3] = *(__half2*)&xvB.w;

        const uint4* eaA4 = (const uint4*)(g_eah + (size_t)p * 12);
        const uint4* eaB4 = (const uint4*)(g_eah + (size_t)(p + 1) * 12);
        uint4 ua0 = eaA4[0], ua1 = eaA4[1], ua2 = eaA4[2];
        uint4 ub0 = eaB4[0], ub1 = eaB4[1], ub2 = eaB4[2];
        __half2 eaA[10], eaB[10];
        eaA[0] = *(__half2*)&ua0.x; eaA[1] = *(__half2*)&ua0.y;
        eaA[2] = *(__half2*)&ua0.z; eaA[3] = *(__half2*)&ua0.w;
        eaA[4] = *(__half2*)&ua1.x; eaA[5] = *(__half2*)&ua1.y;
        eaA[6] = *(__half2*)&ua1.z; eaA[7] = *(__half2*)&ua1.w;
        eaA[8] = *(__half2*)&ua2.x; eaA[9] = *(__half2*)&ua2.y;
        eaB[0] = *(__half2*)&ub0.x; eaB[1] = *(__half2*)&ub0.y;
        eaB[2] = *(__half2*)&ub0.z; eaB[3] = *(__half2*)&ub0.w;
        eaB[4] = *(__half2*)&ub1.x; eaB[5] = *(__half2*)&ub1.y;
        eaB[6] = *(__half2*)&ub1.z; eaB[7] = *(__half2*)&ub1.w;
        eaB[8] = *(__half2*)&ub2.x; eaB[9] = *(__half2*)&ub2.y;

        __half2 mA[4] = {crx2[0], crx2[1], crx2[2], crx2[3]};
        __half2 mB[4] = {crx2[0], crx2[1], crx2[2], crx2[3]};
        #pragma unroll
        for (int k = 0; k < 10; ++k) {
            #pragma unroll
            for (int j2 = 0; j2 < 4; ++j2) {
                mA[j2] = __hfma2(eaA[k], Brg2[k][j2], mA[j2]);
                mB[j2] = __hfma2(eaB[k], Brg2[k][j2], mB[j2]);
            }
        }

        __half2 sA2 = zero2, sB2 = zero2;
        #pragma unroll
        for (int j2 = 0; j2 < 4; ++j2) {
            __half2 vA = __hadd2(mA[j2], xlA[j2]);
            __half2 lkA = __hfma2(__hmin2(vA, zero2), fifth2, __hmax2(vA, zero2));
            sA2 = __hfma2(lkA, attr2[j2], sA2);
            __half2 vB = __hadd2(mB[j2], xlB[j2]);
            __half2 lkB = __hfma2(__hmin2(vB, zero2), fifth2, __hmax2(vB, zero2));
            sB2 = __hfma2(lkB, attr2[j2], sB2);
        }
        float2 sfA = __half22float2(sA2);
        float2 sfB = __half22float2(sB2);
        float sA = sfA.x + sfA.y;
        float sB = sfB.x + sfB.y;
        sA += __shfl_xor_sync(0xffffffffu, sA, 1);
        sB += __shfl_xor_sync(0xffffffffu, sB, 1);
        sA += __shfl_xor_sync(0xffffffffu, sA, 2);
        sB += __shfl_xor_sync(0xffffffffu, sB, 2);
        float wA = __expf(sA);
        float wB = __expf(sB);
        den += wA + wB;
        #pragma unroll
        for (int j2 = 0; j2 < 4; ++j2) {
            float2 xfA = __half22float2(xlA[j2]);
            float2 xfB = __half22float2(xlB[j2]);
            accv[2 * j2]     = fmaf(wA, xfA.x, fmaf(wB, xfB.x, accv[2 * j2]));
            accv[2 * j2 + 1] = fmaf(wA, xfA.y, fmaf(wB, xfB.y, accv[2 * j2 + 1]));
        }
    }

    // ---- tail edge ----
    if (p < s1) {
        int sn = g_srcs[p];
        uint4 xv = *(const uint4*)(g_xlh + (size_t)sn * 256 + c0);
        __half2 xl2[4];
        xl2[0] = *(__half2*)&xv.x; xl2[1] = *(__half2*)&xv.y;
        xl2[2] = *(__half2*)&xv.z; xl2[3] = *(__half2*)&xv.w;
        const uint4* ea4 = (const uint4*)(g_eah + (size_t)p * 12);
        uint4 u0 = ea4[0], u1 = ea4[1], u2 = ea4[2];
        __half2 ea[10];
        ea[0] = *(__half2*)&u0.x; ea[1] = *(__half2*)&u0.y;
        ea[2] = *(__half2*)&u0.z; ea[3] = *(__half2*)&u0.w;
        ea[4] = *(__half2*)&u1.x; ea[5] = *(__half2*)&u1.y;
        ea[6] = *(__half2*)&u1.z; ea[7] = *(__half2*)&u1.w;
        ea[8] = *(__half2*)&u2.x; ea[9] = *(__half2*)&u2.y;

        __half2 m2[4] = {crx2[0], crx2[1], crx2[2], crx2[3]};
        #pragma unroll
        for (int k = 0; k < 10; ++k)
            #pragma unroll
            for (int j2 = 0; j2 < 4; ++j2)
                m2[j2] = __hfma2(ea[k], Brg2[k][j2], m2[j2]);

        __half2 s2 = zero2;
        #pragma unroll
        for (int j2 = 0; j2 < 4; ++j2) {
            __half2 v2 = __hadd2(m2[j2], xl2[j2]);
            __half2 lk = __hfma2(__hmin2(v2, zero2), fifth2, __hmax2(v2, zero2));
            s2 = __hfma2(lk, attr2[j2], s2);
        }
        float2 sf = __half22float2(s2);
        float s = sf.x + sf.y;
        s += __shfl_xor_sync(0xffffffffu, s, 1);
        s += __shfl_xor_sync(0xffffffffu, s, 2);
        float w = __expf(s);
        den += w;
        #pragma unroll
        for (int j2 = 0; j2 < 4; ++j2) {
            float2 xf = __half22float2(xl2[j2]);
            accv[2 * j2]     = fmaf(w, xf.x, accv[2 * j2]);
            accv[2 * j2 + 1] = fmaf(w, xf.y, accv[2 * j2 + 1]);
        }
    }

    float invden = 1.f / (den + 1e-16f);

    float4 cb0 = *(const float4*)(conv_b + layer * 256 + c0);
    float4 cb1 = *(const float4*)(conv_b + layer * 256 + c0 + 4);
    float4 g0  = *(const float4*)(bng + layer * 256 + c0);
    float4 g1  = *(const float4*)(bng + layer * 256 + c0 + 4);
    float4 bb0 = *(const float4*)(bnb + layer * 256 + c0);
    float4 bb1 = *(const float4*)(bnb + layer * 256 + c0 + 4);
    float4 rm0 = *(const float4*)(bnrm + layer * 256 + c0);
    float4 rm1 = *(const float4*)(bnrm + layer * 256 + c0 + 4);
    float4 rv0 = *(const float4*)(bnrv + layer * 256 + c0);
    float4 rv1 = *(const float4*)(bnrv + layer * 256 + c0 + 4);
    float cb[8] = {cb0.x, cb0.y, cb0.z, cb0.w, cb1.x, cb1.y, cb1.z, cb1.w};
    float gg[8] = {g0.x, g0.y, g0.z, g0.w, g1.x, g1.y, g1.z, g1.w};
    float bbv[8] = {bb0.x, bb0.y, bb0.z, bb0.w, bb1.x, bb1.y, bb1.z, bb1.w};
    float rm[8] = {rm0.x, rm0.y, rm0.z, rm0.w, rm1.x, rm1.y, rm1.z, rm1.w};
    float rv[8] = {rv0.x, rv0.y, rv0.z, rv0.w, rv1.x, rv1.y, rv1.z, rv1.w};

    size_t base = (size_t)n * 256 + c0;
    __half resh[8], resl[8];
    if (layer >= 1) {
        *(uint4*)resh = *(const uint4*)(&g_hh[hin][base]);
        *(uint4*)resl = *(const uint4*)(&g_hl[hin][base]);
    }
    __half oh[8], ol[8];
    #pragma unroll
    for (int j = 0; j < 8; ++j) {
        float sc = gg[j] * rsqrtf(rv[j] + 1e-5f);
        float sh = bbv[j] - rm[j] * sc;
        float v = accv[j] * invden + cb[j];
        v = v * sc + sh;
        v = v >= 0.f ? v : 0.01f * v;
        if (layer >= 1) v += __half2float(resh[j]) + __half2float(resl[j]);
        split_f16(v, oh[j], ol[j]);
    }
    *(uint4*)(&g_hh[hout][base]) = *(const uint4*)oh;
    *(uint4*)(&g_hl[hout][base]) = *(const uint4*)ol;
}

// ---------------- head: out = t @ W2 + b2 ----------------
__global__ void head2_kernel(const float* __restrict__ W2, const float* __restrict__ b2,
                             float* __restrict__ out) {
    __shared__ float w[128];
    int tid = threadIdx.x;
    if (tid < 128) w[tid] = W2[tid];
    __syncthreads();
    int n = blockIdx.x * 256 + tid;
    if (n >= NN) return;
    float s = b2[0];
    const float* tp = g_t + (size_t)n * 128;
    #pragma unroll
    for (int j = 0; j < 128; ++j) s = fmaf(tp[j], w[j], s);
    out[n] = s;
}

// ---------------- launch ----------------
extern "C" void kernel_launch(void* const* d_in, const int* in_sizes, int n_in,
                              void* d_out, int out_size) {
    const float* x      = (const float*)d_in[0];
    const int*   ei     = (const int*)d_in[1];
    const float* eattr  = (const float*)d_in[2];
    const float* nW     = (const float*)d_in[3];
    const float* nb     = (const float*)d_in[4];
    const float* eW     = (const float*)d_in[5];
    const float* eb     = (const float*)d_in[6];
    const float* Wl     = (const float*)d_in[7];
    const float* bl     = (const float*)d_in[8];
    const float* Wr     = (const float*)d_in[9];
    const float* br     = (const float*)d_in[10];
    const float* We     = (const float*)d_in[11];
    const float* att    = (const float*)d_in[12];
    const float* conv_b = (const float*)d_in[13];
    const float* Weu    = (const float*)d_in[14];
    const float* beu    = (const float*)d_in[15];
    const float* bng    = (const float*)d_in[16];
    const float* bnb    = (const float*)d_in[17];
    const float* bnrm   = (const float*)d_in[18];
    const float* bnrv   = (const float*)d_in[19];
    const float* oW1    = (const float*)d_in[20];
    const float* ob1    = (const float*)d_in[21];
    const float* oW2    = (const float*)d_in[22];
    const float* ob2    = (const float*)d_in[23];

    const int* srcp = ei;
    const int* dstp = ei + EE;

    static cudaStream_t s_side = 0;
    static cudaEvent_t  e_fork = 0, e_join = 0;
    static int init_done = 0;
    if (!init_done) {
        cudaFuncSetAttribute(mma_gemm, cudaFuncAttributeMaxDynamicSharedMemorySize,
                             GSMEM_BYTES);
        cudaStreamCreateWithFlags(&s_side, cudaStreamNonBlocking);
        cudaEventCreateWithFlags(&e_fork, cudaEventDisableTiming);
        cudaEventCreateWithFlags(&e_join, cudaEventDisableTiming);
        init_done = 1;
    }

    const int MT = (NN + 127) / 128;   // 235
    dim3 gemm_grid(MT, 4);
    dim3 head_grid(MT, 1);

    // ---- fork: prolog prep chain runs on the side stream while the main
    //      stream does wprep -> encoder -> GEMM L0. They touch disjoint data
    //      and join before attention L0. ----
    cudaEventRecord(e_fork, 0);
    cudaStreamWaitEvent(s_side, e_fork, 0);

    // side stream: CSR build + edge arrays + edge-matrix chain
    zero_kernel<<<(NN + 256) / 256, 256, 0, s_side>>>();
    count_kernel<<<(EE + 255) / 256, 256, 0, s_side>>>(dstp);
    scan_kernel<<<1, 1024, 0, s_side>>>();
    fill_kernel<<<(EE + 255) / 256, 256, 0, s_side>>>(dstp);
    sort_kernel<<<(NN + 127) / 128, 128, 0, s_side>>>();
    gather_kernel<<<(EE + 255) / 256, 256, 0, s_side>>>(srcp, eattr);
    chain_kernel<<<1, 256, 0, s_side>>>(eW, eb, Weu, beu);
    bmat_kernel<<<NLAY, 256, 0, s_side>>>(We);
    cudaEventRecord(e_join, s_side);

    // main stream: weight prep + encoder + layer-0 GEMM
    wprep_kernel<<<3200, 256>>>(Wl, Wr, oW1);
    encoder_kernel<<<NN, 256>>>(x, nW, nb);
    mma_gemm<<<gemm_grid, 256, GSMEM_BYTES>>>(0, 0, bl, br, 0, 1.0f, 1);

    // join before attention L0
    cudaStreamWaitEvent(0, e_join, 0);

    int cur = 0;
    attn_fused<<<(NN + 3) / 4, 128>>>(0, cur, att, conv_b, bng, bnb, bnrm, bnrv);
    cur ^= 1;
    for (int i = 1; i < NLAY; ++i) {
        mma_gemm<<<gemm_grid, 256, GSMEM_BYTES>>>(cur, i * 512, bl + i * 256, br + i * 256,
                                                  /*outmode=*/0, /*slope=*/1.0f, /*passes=*/1);
        attn_fused<<<(NN + 3) / 4, 128>>>(i, cur, att, conv_b, bng, bnb, bnrm, bnrv);
        cur ^= 1;
    }

    // output head (fp32-grade 3-pass)
    mma_gemm<<<head_grid, 256, GSMEM_BYTES>>>(cur, NLAY * 512, ob1, (const float*)0,
                                              /*outmode=*/1, /*slope=*/0.01f, /*passes=*/3);
    head2_kernel<<<(NN + 255) / 256, 256>>>(oW2, ob2, (float*)d_out);
}